// round 12
// baseline (speedup 1.0000x reference)
#include <cuda_runtime.h>
#include <stdint.h>

// X (B=4, L=8192, D=32, N=32) fp32, cumsum along L (axis=1).
// Inner = D*N = 1024 contiguous floats per (b,l).
#define BB      4
#define LL      8192
#define INNER   1024
#define SEGW    256                    // lanes per CTA (segment width)
#define NSEG    (INNER / SEGW)         // 4 segments
#define CHUNK   32                     // L rows per tile
#define NT      (LL / CHUNK)           // 256 L-tiles per chain
#define NCHAIN  (BB * NSEG)            // 16 independent (b,seg) chains
#define NTILES  (NCHAIN * NT)          // 4096 tiles per launch
#define GRID    592                    // persistent CTAs (4/SM x 148 SMs)
#define TPL     (NTILES + GRID)        // tickets consumed per launch (exact)
#define LOOKW   4                      // lookback window (x2 pipelined)

// Decoupled-lookback state: packed {flag:32 | value_bits:32} per (tile, lane).
// Flag+value travel in ONE 8-byte relaxed access => no fences needed anywhere.
//   flag <  fbase   : stale (earlier launch)
//   flag == fbase   : aggregate available
//   flag == fbase+1 : inclusive prefix available
// fbase = 2*(ticket/TPL) + 2; g_ticket is monotonic forever (no init kernel).
__device__ unsigned long long g_state[(size_t)NTILES * SEGW];   // 8 MiB
__device__ unsigned int g_ticket = 0;

__device__ __forceinline__ unsigned long long ld_relaxed_u64(const unsigned long long* p) {
    unsigned long long v;
    asm volatile("ld.relaxed.gpu.global.b64 %0, [%1];" : "=l"(v) : "l"(p));
    return v;
}
__device__ __forceinline__ void st_relaxed_u64(unsigned long long* p, unsigned long long v) {
    asm volatile("st.relaxed.gpu.global.b64 [%0], %1;" :: "l"(p), "l"(v));
}
__device__ __forceinline__ unsigned long long pack_fv(unsigned int flag, float val) {
    return ((unsigned long long)flag << 32) | (unsigned long long)__float_as_uint(val);
}
__device__ __forceinline__ void cp_async16(uint32_t smem_addr, const void* gmem) {
    asm volatile("cp.async.cg.shared.global [%0], [%1], 16;"
                 :: "r"(smem_addr), "l"(gmem));
}
__device__ __forceinline__ void cp_async_commit() {
    asm volatile("cp.async.commit_group;");
}
__device__ __forceinline__ void cp_async_wait0() {
    asm volatile("cp.async.wait_group 0;");
}

// Element index of row 0, lane 0 of a tile.
__device__ __forceinline__ size_t tile_row0(int tloc) {
    const int chain = tloc & (NCHAIN - 1);
    const int ltile = tloc >> 4;               // NCHAIN = 16
    const int b     = chain >> 2;              // NSEG = 4
    const int seg   = chain & 3;
    return ((size_t)b * LL + (size_t)ltile * CHUNK) * INNER + (size_t)seg * SEGW;
}

__global__ __launch_bounds__(SEGW, 4)
void scan_kernel(const float* __restrict__ X, float* __restrict__ Y) {
    __shared__ float s_buf[CHUNK * SEGW];      // 32 KB staging
    __shared__ unsigned int s_t;

    const int tid  = (int)threadIdx.x;
    const int lane = tid;

    uint32_t s_base;
    asm("{ .reg .u64 t; cvta.to.shared.u64 t, %1; cvt.u32.u64 %0, t; }"
        : "=r"(s_base) : "l"(s_buf));

    if (tid == 0) s_t = atomicAdd(&g_ticket, 1u);
    __syncthreads();

    const unsigned int t0    = s_t;
    const unsigned int epoch = t0 / TPL;                 // launch-unique
    const unsigned int lb    = epoch * TPL;              // launch ticket base
    const unsigned int fbase = epoch * 2u + 2u;          // agg flag; incl = +1
    int tloc = (int)(t0 - lb);
    if (tloc >= NTILES) return;                          // terminating ticket

    // cp.async sweep geometry: 8 sweeps of 4 KB; thread covers 16 B per sweep.
    const int sub  = tid >> 6;                 // row-within-4 group
    const int colb = (tid & 63) * 16;          // byte column within row
    const uint32_t s_dst0 = s_base + (uint32_t)(sub * 1024 + colb);

    size_t row0 = tile_row0(tloc);             // hoisted, reused for stores

    // Prologue: prefetch first tile.
    {
        const char* src = (const char*)(X + row0);
#pragma unroll
        for (int s = 0; s < CHUNK / 4; ++s)
            cp_async16(s_dst0 + (uint32_t)s * 4096u,
                       src + (size_t)(s * 4 + sub) * (INNER * 4) + colb);
        cp_async_commit();
    }

    for (;;) {
        cp_async_wait0();
        __syncthreads();                       // staged tile visible to all

        // ---- load from smem + local inclusive scan ----
        float v[CHUNK];
#pragma unroll
        for (int i = 0; i < CHUNK; ++i) v[i] = s_buf[i * SEGW + lane];
#pragma unroll
        for (int i = 1; i < CHUNK; ++i) v[i] += v[i - 1];
        const float total = v[CHUNK - 1];

        const int chain = tloc & (NCHAIN - 1);
        const int ltile = tloc >> 4;
        const size_t chain_base = ((size_t)chain * NT) * SEGW + lane;
        unsigned long long* my_state = &g_state[chain_base + (size_t)ltile * SEGW];

        // Publish aggregate (inclusive for ltile 0) — fence-free packed word.
        st_relaxed_u64(my_state,
                       pack_fv(ltile == 0 ? fbase + 1u : fbase, total));

        // Next ticket. (WAR on s_t safe: last read was before the top barrier.)
        if (tid == 0) s_t = atomicAdd(&g_ticket, 1u);
        __syncthreads();                       // LDS drained + s_t visible
        const int tloc1 = (int)(s_t - lb);

        size_t row0n = 0;
        if (tloc1 < NTILES) {
            row0n = tile_row0(tloc1);
            const char* src = (const char*)(X + row0n);
#pragma unroll
            for (int s = 0; s < CHUNK / 4; ++s)
                cp_async16(s_dst0 + (uint32_t)s * 4096u,
                           src + (size_t)(s * 4 + sub) * (INNER * 4) + colb);
            cp_async_commit();
        }

        // ---- pipelined decoupled lookback (double window of LOOKW) ----
        float excl = 0.0f;
        if (ltile != 0) {
            const unsigned long long* st_row = &g_state[chain_base];
            int pt = ltile - 1;                        // next index to consume
            unsigned long long w0[LOOKW];
            int n0 = (pt + 1 < LOOKW) ? (pt + 1) : LOOKW;
#pragma unroll
            for (int j = 0; j < LOOKW; ++j)
                if (j < n0) w0[j] = ld_relaxed_u64(st_row + (size_t)(pt - j) * SEGW);

            for (;;) {
                // Speculatively issue the next window before consuming w0.
                const int ptB = pt - n0;
                const int n1 = (ptB >= 0)
                             ? ((ptB + 1 < LOOKW) ? (ptB + 1) : LOOKW) : 0;
                unsigned long long w1[LOOKW];
#pragma unroll
                for (int j = 0; j < LOOKW; ++j)
                    if (j < n1) w1[j] = ld_relaxed_u64(st_row + (size_t)(ptB - j) * SEGW);

                // Consume w0.
                int consumed = 0;
                bool done = false, stale = false;
#pragma unroll
                for (int j = 0; j < LOOKW; ++j) {
                    if (j >= n0 || done || stale) continue;
                    const unsigned int f = (unsigned int)(w0[j] >> 32);
                    if (f < fbase) { stale = true; continue; }
                    excl += __uint_as_float((unsigned int)w0[j]);
                    ++consumed;
                    if (f == fbase + 1u) done = true;
                }
                if (done) break;
                pt -= consumed;
                if (consumed == n0 && n1 > 0) {        // full hit: swap windows
#pragma unroll
                    for (int j = 0; j < LOOKW; ++j) w0[j] = w1[j];
                    n0 = n1;
                } else {                               // stale mid-window: reload
                    if (consumed == 0) __nanosleep(32);
                    n0 = (pt + 1 < LOOKW) ? (pt + 1) : LOOKW;
#pragma unroll
                    for (int j = 0; j < LOOKW; ++j)
                        if (j < n0) w0[j] = ld_relaxed_u64(st_row + (size_t)(pt - j) * SEGW);
                }
            }
            st_relaxed_u64(my_state, pack_fv(fbase + 1u, excl + total));
        }

        // ---- store outputs (coalesced) ----
        {
            float* q = Y + row0 + lane;
#pragma unroll
            for (int i = 0; i < CHUNK; ++i) q[(size_t)i * INNER] = v[i] + excl;
        }

        if (tloc1 >= NTILES) break;
        tloc = tloc1;
        row0 = row0n;
    }
}

extern "C" void kernel_launch(void* const* d_in, const int* in_sizes, int n_in,
                              void* d_out, int out_size) {
    const float* X = (const float*)d_in[0];
    float*       Y = (float*)d_out;
    (void)in_sizes; (void)n_in; (void)out_size;

    scan_kernel<<<GRID, SEGW>>>(X, Y);
}

// round 13
// speedup vs baseline: 1.0999x; 1.0999x over previous
#include <cuda_runtime.h>
#include <stdint.h>

// X (B=4, L=8192, D=32, N=32) fp32, cumsum along L (axis=1).
// Inner = D*N = 1024 contiguous floats per (b,l).
#define BB      4
#define LL      8192
#define INNER   1024
#define SEGW    256                    // lanes per CTA (segment width)
#define NSEG    (INNER / SEGW)         // 4 segments
#define CHUNK   32                     // L rows per tile
#define NT      (LL / CHUNK)           // 256 L-tiles per chain
#define NCHAIN  (BB * NSEG)            // 16 independent (b,seg) chains
#define NTILES  (NCHAIN * NT)          // 4096 tiles per launch
#define GRID    592                    // persistent CTAs (4/SM x 148 SMs)
#define TPL     (NTILES + GRID)        // tickets consumed per launch (exact)
#define LOOKW   6                      // lookback window (independent loads)

// Decoupled-lookback state: packed {flag:32 | value_bits:32} per (tile, lane).
// Flag+value travel in ONE 8-byte relaxed access => no fences needed anywhere.
//   flag <  fbase   : stale (earlier launch)
//   flag == fbase   : aggregate available
//   flag == fbase+1 : inclusive prefix available
// fbase = 2*(ticket/TPL) + 2; g_ticket is monotonic forever (no init kernel).
__device__ unsigned long long g_state[(size_t)NTILES * SEGW];   // 8 MiB
__device__ unsigned int g_ticket = 0;

__device__ __forceinline__ unsigned long long ld_relaxed_u64(const unsigned long long* p) {
    unsigned long long v;
    asm volatile("ld.relaxed.gpu.global.b64 %0, [%1];" : "=l"(v) : "l"(p));
    return v;
}
__device__ __forceinline__ void st_relaxed_u64(unsigned long long* p, unsigned long long v) {
    asm volatile("st.relaxed.gpu.global.b64 [%0], %1;" :: "l"(p), "l"(v));
}
// Evict-first streaming store: output is write-once, never re-read by the
// kernel — keep it from evicting the lookback state out of L2.
__device__ __forceinline__ void st_cs_f32(float* p, float v) {
    asm volatile("st.global.cs.f32 [%0], %1;" :: "l"(p), "f"(v));
}
__device__ __forceinline__ unsigned long long pack_fv(unsigned int flag, float val) {
    return ((unsigned long long)flag << 32) | (unsigned long long)__float_as_uint(val);
}
__device__ __forceinline__ void cp_async16(uint32_t smem_addr, const void* gmem) {
    asm volatile("cp.async.cg.shared.global [%0], [%1], 16;"
                 :: "r"(smem_addr), "l"(gmem));
}
__device__ __forceinline__ void cp_async_commit() {
    asm volatile("cp.async.commit_group;");
}
__device__ __forceinline__ void cp_async_wait0() {
    asm volatile("cp.async.wait_group 0;");
}

// Element index of row 0, lane 0 of a tile.
__device__ __forceinline__ size_t tile_row0(int tloc) {
    const int chain = tloc & (NCHAIN - 1);
    const int ltile = tloc >> 4;               // NCHAIN = 16
    const int b     = chain >> 2;              // NSEG = 4
    const int seg   = chain & 3;
    return ((size_t)b * LL + (size_t)ltile * CHUNK) * INNER + (size_t)seg * SEGW;
}

__global__ __launch_bounds__(SEGW, 4)
void scan_kernel(const float* __restrict__ X, float* __restrict__ Y) {
    __shared__ float s_buf[CHUNK * SEGW];      // 32 KB staging
    __shared__ unsigned int s_t;

    const int tid  = (int)threadIdx.x;
    const int lane = tid;

    uint32_t s_base;
    asm("{ .reg .u64 t; cvta.to.shared.u64 t, %1; cvt.u32.u64 %0, t; }"
        : "=r"(s_base) : "l"(s_buf));

    if (tid == 0) s_t = atomicAdd(&g_ticket, 1u);
    __syncthreads();

    const unsigned int t0    = s_t;
    const unsigned int epoch = t0 / TPL;                 // launch-unique
    const unsigned int lb    = epoch * TPL;              // launch ticket base
    const unsigned int fbase = epoch * 2u + 2u;          // agg flag; incl = +1
    int tloc = (int)(t0 - lb);
    if (tloc >= NTILES) return;                          // terminating ticket

    // cp.async sweep geometry: 8 sweeps of 4 KB; thread covers 16 B per sweep.
    const int sub  = tid >> 6;                 // row-within-4 group
    const int colb = (tid & 63) * 16;          // byte column within row
    const uint32_t s_dst0 = s_base + (uint32_t)(sub * 1024 + colb);

    // Prologue: prefetch first tile.
    {
        const char* src = (const char*)(X + tile_row0(tloc));
#pragma unroll
        for (int s = 0; s < CHUNK / 4; ++s)
            cp_async16(s_dst0 + (uint32_t)s * 4096u,
                       src + (size_t)(s * 4 + sub) * (INNER * 4) + colb);
        cp_async_commit();
    }

    for (;;) {
        cp_async_wait0();
        __syncthreads();                       // staged tile visible to all

        // ---- load from smem + local inclusive scan ----
        float v[CHUNK];
#pragma unroll
        for (int i = 0; i < CHUNK; ++i) v[i] = s_buf[i * SEGW + lane];
#pragma unroll
        for (int i = 1; i < CHUNK; ++i) v[i] += v[i - 1];
        const float total = v[CHUNK - 1];

        const int chain = tloc & (NCHAIN - 1);
        const int ltile = tloc >> 4;
        const size_t chain_base = ((size_t)chain * NT) * SEGW + lane;
        unsigned long long* my_state = &g_state[chain_base + (size_t)ltile * SEGW];

        // Publish aggregate (inclusive for ltile 0) — fence-free packed word.
        st_relaxed_u64(my_state,
                       pack_fv(ltile == 0 ? fbase + 1u : fbase, total));

        // Next ticket. (WAR on s_t safe: last read before the top barrier.)
        if (tid == 0) s_t = atomicAdd(&g_ticket, 1u);
        __syncthreads();                       // LDS drained + s_t visible
        const int tloc1 = (int)(s_t - lb);

        // Prefetch next tile into the reusable buffer; overlaps lookback.
        if (tloc1 < NTILES) {
            const char* src = (const char*)(X + tile_row0(tloc1));
#pragma unroll
            for (int s = 0; s < CHUNK / 4; ++s)
                cp_async16(s_dst0 + (uint32_t)s * 4096u,
                           src + (size_t)(s * 4 + sub) * (INNER * 4) + colb);
            cp_async_commit();
        }

        // ---- decoupled lookback (LOOKW independent loads per round) ----
        float excl = 0.0f;
        if (ltile != 0) {
            const unsigned long long* st_row = &g_state[chain_base];
            int pt = ltile - 1;
            for (;;) {
                unsigned long long w[LOOKW];
                const int n = (pt + 1 < LOOKW) ? (pt + 1) : LOOKW;
#pragma unroll
                for (int j = 0; j < LOOKW; ++j)
                    if (j < n) w[j] = ld_relaxed_u64(st_row + (size_t)(pt - j) * SEGW);

                int consumed = 0;
                bool done = false;
#pragma unroll
                for (int j = 0; j < LOOKW; ++j) {
                    if (j >= n || done) continue;
                    unsigned int f = (unsigned int)(w[j] >> 32);
                    if (f < fbase) break;                      // stale: stop
                    excl += __uint_as_float((unsigned int)w[j]);
                    ++consumed;
                    if (f == fbase + 1u) done = true;          // found inclusive
                }
                pt -= consumed;
                if (done) break;
                if (consumed == 0) __nanosleep(32);
            }
            st_relaxed_u64(my_state, pack_fv(fbase + 1u, excl + total));
        }

        // ---- store outputs (coalesced, streaming/evict-first) ----
        {
            float* q = Y + tile_row0(tloc) + lane;
#pragma unroll
            for (int i = 0; i < CHUNK; ++i) st_cs_f32(q + (size_t)i * INNER,
                                                      v[i] + excl);
        }

        if (tloc1 >= NTILES) break;
        tloc = tloc1;
    }
}

extern "C" void kernel_launch(void* const* d_in, const int* in_sizes, int n_in,
                              void* d_out, int out_size) {
    const float* X = (const float*)d_in[0];
    float*       Y = (float*)d_out;
    (void)in_sizes; (void)n_in; (void)out_size;

    scan_kernel<<<GRID, SEGW>>>(X, Y);
}